// round 15
// baseline (speedup 1.0000x reference)
#include <cuda_runtime.h>
#include <cuda_bf16.h>
#include <cuda_fp8.h>
#include <cstdint>

// ---------------------------------------------------------------------------
// Problem constants
// ---------------------------------------------------------------------------
#define N_ROWS 16384
#define K_ROWS 2048
#define D_DIM  1024
#define TOT_ROWS (N_ROWS + K_ROWS)

#define BM 128
#define BN 128
#define BK 128                  // fp8 -> 128 B per smem row (SW128 atom)
#define KT_PER_TILE 8           // D / BK
#define NTILES 2048             // (N/BM) * (K/BN)
#define TN 16                   // tiles along n
#define GRID_P 296              // persistent CTAs (2 per SM, all co-resident)
#define NWARPS_G (GRID_P * 8)   // 2368 warps for the convert phase
#define STAGES 3
#define A_STAGE_BYTES (BM * 128)                      // 16 KB
#define B_STAGE_BYTES (BN * 128)                      // 16 KB
#define STAGE_BYTES (A_STAGE_BYTES + B_STAGE_BYTES)   // 32 KB
#define SM_ALLOC (STAGES * STAGE_BYTES)               // 96 KB -> 2 CTAs/SM

// fp8 mirrors + squared norms (device globals: allocation-free scratch)
// feat scaled by 2 (exact), cent scaled by 256 (exact):
//   acc = 512*feat.cent -> out = fs + cs - acc/256
__device__ uint8_t g_feat_f8[(size_t)N_ROWS * D_DIM];   // 16 MB
__device__ uint8_t g_cent_f8[(size_t)K_ROWS * D_DIM];   //  2 MB
__device__ float g_feat_sq[N_ROWS];
__device__ float g_cent_sq[K_ROWS];
// generation-based grid barrier counter (monotonic; exactly GRID_P adds per
// kernel execution -> target arithmetic is exact across graph replays)
__device__ unsigned long long g_ctr = 0ULL;

// ---------------------------------------------------------------------------
// helpers
// ---------------------------------------------------------------------------
__device__ __forceinline__ void cp_async16(uint32_t saddr, const void* gaddr) {
    asm volatile("cp.async.cg.shared.global [%0], [%1], 16;" :: "r"(saddr), "l"(gaddr));
}

__device__ __forceinline__ void ldsm_x4(uint32_t* r, uint32_t addr) {
    asm volatile("ldmatrix.sync.aligned.m8n8.x4.shared.b16 {%0,%1,%2,%3}, [%4];"
                 : "=r"(r[0]), "=r"(r[1]), "=r"(r[2]), "=r"(r[3]) : "r"(addr));
}

__device__ __forceinline__ void mma_fp8(float* c, const uint32_t* a,
                                        uint32_t b0, uint32_t b1) {
    asm volatile(
        "mma.sync.aligned.m16n8k32.row.col.f32.e4m3.e4m3.f32 "
        "{%0,%1,%2,%3}, {%4,%5,%6,%7}, {%8,%9}, {%0,%1,%2,%3};\n"
        : "+f"(c[0]), "+f"(c[1]), "+f"(c[2]), "+f"(c[3])
        : "r"(a[0]), "r"(a[1]), "r"(a[2]), "r"(a[3]), "r"(b0), "r"(b1));
}

__device__ __forceinline__ void mbar_wait(uint32_t mbar, uint32_t parity) {
    uint32_t done;
    asm volatile(
        "{\n\t.reg .pred p;\n\t"
        "mbarrier.try_wait.parity.acquire.cta.shared::cta.b64 p, [%1], %2;\n\t"
        "selp.b32 %0, 1, 0, p;\n\t}"
        : "=r"(done) : "r"(mbar), "r"(parity) : "memory");
    if (!done) {
        asm volatile(
            "{\n\t.reg .pred P1;\n\t"
            "WL_%=:\n\t"
            "mbarrier.try_wait.parity.acquire.cta.shared::cta.b64 P1, [%0], %1, 0x989680;\n\t"
            "@P1 bra.uni WD_%=;\n\t"
            "bra.uni WL_%=;\n\t"
            "WD_%=:\n\t}"
            :: "r"(mbar), "r"(parity) : "memory");
    }
}

// ---------------------------------------------------------------------------
// Fused persistent kernel:
//   Phase 1: fp32 -> fp8 conversion + row squared-norms (all warps).
//   Grid barrier (generation-based, replay-safe).
//   Phase 2: FP8 distance GEMM (R9 proven-best mainloop, verbatim).
// ---------------------------------------------------------------------------
__global__ void __launch_bounds__(256, 2)
fused_dist_kernel(const float* __restrict__ feat,
                  const float* __restrict__ cent,
                  float* __restrict__ out) {
    extern __shared__ __align__(1024) char smem[];
    __shared__ __align__(8) uint64_t mbars[2 * STAGES];   // [full0..2, empty0..2]
    const uint32_t smem_u = (uint32_t)__cvta_generic_to_shared(smem);
    const uint32_t mb_u   = (uint32_t)__cvta_generic_to_shared(mbars);

    const int tid  = threadIdx.x;
    const int warp = tid >> 5;
    const int lane = tid & 31;
    const int bid  = blockIdx.x;

    if (tid == 0) {
#pragma unroll
        for (int s = 0; s < STAGES; s++) {
            asm volatile("mbarrier.init.shared.b64 [%0], 256;"
                         :: "r"(mb_u + s * 8) : "memory");                 // full
            asm volatile("mbarrier.init.shared.b64 [%0], 8;"
                         :: "r"(mb_u + (STAGES + s) * 8) : "memory");      // empty
        }
    }

    // ================= Phase 1: convert + norms =================
    for (int grow = bid * 8 + warp; grow < TOT_ROWS; grow += NWARPS_G) {
        const float* src;
        uint8_t* dst;
        float* sq;
        int row;
        float scale;
        if (grow < N_ROWS) { src = feat; dst = g_feat_f8; sq = g_feat_sq; row = grow; scale = 2.f; }
        else               { src = cent; dst = g_cent_f8; sq = g_cent_sq; row = grow - N_ROWS; scale = 256.f; }

        const float4* p = reinterpret_cast<const float4*>(src) + (size_t)row * (D_DIM / 4);
        uint2* d = reinterpret_cast<uint2*>(dst + (size_t)row * D_DIM);
        float s = 0.f;
#pragma unroll
        for (int it = 0; it < 4; it++) {
            int c = it * 64 + lane * 2;
            float4 v0 = p[c];
            float4 v1 = p[c + 1];
            s += v0.x * v0.x + v0.y * v0.y + v0.z * v0.z + v0.w * v0.w;
            s += v1.x * v1.x + v1.y * v1.y + v1.z * v1.z + v1.w * v1.w;
            uint16_t a0 = __nv_cvt_float2_to_fp8x2(make_float2(v0.x * scale, v0.y * scale),
                                                   __NV_SATFINITE, __NV_E4M3);
            uint16_t a1 = __nv_cvt_float2_to_fp8x2(make_float2(v0.z * scale, v0.w * scale),
                                                   __NV_SATFINITE, __NV_E4M3);
            uint16_t a2 = __nv_cvt_float2_to_fp8x2(make_float2(v1.x * scale, v1.y * scale),
                                                   __NV_SATFINITE, __NV_E4M3);
            uint16_t a3 = __nv_cvt_float2_to_fp8x2(make_float2(v1.z * scale, v1.w * scale),
                                                   __NV_SATFINITE, __NV_E4M3);
            uint2 u;
            u.x = (uint32_t)a0 | ((uint32_t)a1 << 16);
            u.y = (uint32_t)a2 | ((uint32_t)a3 << 16);
            d[it * 32 + lane] = u;
        }
#pragma unroll
        for (int o = 16; o > 0; o >>= 1) s += __shfl_xor_sync(0xffffffffu, s, o);
        if (lane == 0) sq[row] = s;
    }

    // ================= Grid barrier (replay-safe) =================
    __threadfence();          // each thread's stores visible gpu-wide
    __syncthreads();          // all CTA threads past their fence
    if (tid == 0) {
        unsigned long long v = atomicAdd(&g_ctr, 1ULL);
        unsigned long long target = (v / GRID_P + 1ULL) * GRID_P;
        unsigned long long c;
        do {
            asm volatile("ld.global.acquire.gpu.u64 %0, [%1];"
                         : "=l"(c) : "l"(&g_ctr) : "memory");
        } while (c < target);
    }
    __syncthreads();

    // ================= Phase 2: GEMM (R9 mainloop) =================
    const int wm = (warp >> 2) * 64;
    const int wn = (warp & 3) * 32;

    // --- producer addressing ---
    const int ld_row = tid >> 1;
    const int ld_q0  = (tid & 1) * 4;
    const uint32_t ld_sw_row = ld_row * 128;
    const uint32_t ld_rx     = (ld_row & 7) << 4;

    auto produce = [&](int s, int st) {
        const int t  = bid + (st >> 3) * GRID_P;
        const int kt = st & 7;
        const int m0 = (t >> 4) << 7;
        const int n0 = (t & (TN - 1)) << 7;
        const uint32_t abase = smem_u + s * STAGE_BYTES;
        const uint32_t bbase = abase + A_STAGE_BYTES;
        const uint8_t* ag = g_feat_f8 + (size_t)(m0 + ld_row) * D_DIM + kt * BK + ld_q0 * 16;
        const uint8_t* bg = g_cent_f8 + (size_t)(n0 + ld_row) * D_DIM + kt * BK + ld_q0 * 16;
#pragma unroll
        for (int j = 0; j < 4; j++) {
            uint32_t so = ld_sw_row + ((((ld_q0 + j) * 16) ^ ld_rx));
            cp_async16(abase + so, ag + j * 16);
            cp_async16(bbase + so, bg + j * 16);
        }
        asm volatile("cp.async.mbarrier.arrive.noinc.shared::cta.b64 [%0];"
                     :: "r"(mb_u + s * 8) : "memory");
    };

    // --- consumer addressing (constant parts) ---
    const int fr_lo = lane & 15;
    const uint32_t fr_hi16 = (lane >> 4) * 16;

    uint32_t a_rowb[4], a_rx[4], b_rowb[2], b_rx[2];
#pragma unroll
    for (int im = 0; im < 4; im++) {
        int r = wm + im * 16 + fr_lo;
        a_rowb[im] = r * 128;
        a_rx[im]   = (r & 7) << 4;
    }
#pragma unroll
    for (int ib = 0; ib < 2; ib++) {
        int r = wn + ib * 16 + fr_lo;
        b_rowb[ib] = r * 128;
        b_rx[ib]   = (r & 7) << 4;
    }

    float acc[4][4][4] = {};

    const int ntiles = (NTILES - bid + GRID_P - 1) / GRID_P;
    const int nsteps = ntiles * KT_PER_TILE;

    int ps = 0, pph = 1;
    int cs = 0, cph = 0;

#pragma unroll
    for (int k = 0; k < STAGES - 1; k++) {
        mbar_wait(mb_u + (STAGES + ps) * 8, (uint32_t)pph);
        produce(ps, k);
        if (++ps == STAGES) { ps = 0; pph ^= 1; }
    }

    for (int st = 0; st < nsteps; st++) {
        mbar_wait(mb_u + cs * 8, (uint32_t)cph);
        const uint32_t abase = smem_u + cs * STAGE_BYTES;
        const uint32_t bbase = abase + A_STAGE_BYTES;

#pragma unroll
        for (int ks = 0; ks < 4; ks++) {
            const int kse = (ks + warp) & 3;
            const uint32_t kb = kse * 32 + fr_hi16;
            uint32_t a[4][4], bq[2][4];
#pragma unroll
            for (int im = 0; im < 4; im++)
                ldsm_x4(a[im], abase + a_rowb[im] + (kb ^ a_rx[im]));
#pragma unroll
            for (int ib = 0; ib < 2; ib++)
                ldsm_x4(bq[ib], bbase + b_rowb[ib] + (kb ^ b_rx[ib]));
#pragma unroll
            for (int im = 0; im < 4; im++) {
#pragma unroll
                for (int ib = 0; ib < 2; ib++) {
                    mma_fp8(acc[im][2 * ib],     a[im], bq[ib][0], bq[ib][2]);
                    mma_fp8(acc[im][2 * ib + 1], a[im], bq[ib][1], bq[ib][3]);
                }
            }
        }

        if (lane == 0) {
            asm volatile("mbarrier.arrive.shared.b64 _, [%0];"
                         :: "r"(mb_u + (STAGES + cs) * 8) : "memory");
        }
        if (++cs == STAGES) { cs = 0; cph ^= 1; }

        if (st + STAGES - 1 < nsteps) {
            mbar_wait(mb_u + (STAGES + ps) * 8, (uint32_t)pph);
            produce(ps, st + STAGES - 1);
            if (++ps == STAGES) { ps = 0; pph ^= 1; }
        }

        if ((st & 7) == 7) {
            // ---- epilogue; norms read via __ldcg (same-launch cross-CTA) ----
            const int t  = bid + (st >> 3) * GRID_P;
            const int m0 = (t >> 4) << 7;
            const int n0 = (t & (TN - 1)) << 7;
            const float inv = 1.0f / 256.0f;
            const int g = lane >> 2;
            const int tt = lane & 3;
#pragma unroll
            for (int im = 0; im < 4; im++) {
                int gm = m0 + wm + im * 16 + g;
                float fs0 = __ldcg(&g_feat_sq[gm]);
                float fs1 = __ldcg(&g_feat_sq[gm + 8]);
#pragma unroll
                for (int in = 0; in < 4; in++) {
                    int gn = n0 + wn + in * 8 + 2 * tt;
                    float cs0 = __ldcg(&g_cent_sq[gn]);
                    float cs1 = __ldcg(&g_cent_sq[gn + 1]);
                    float2 v0, v1;
                    v0.x = fs0 + cs0 - acc[im][in][0] * inv;
                    v0.y = fs0 + cs1 - acc[im][in][1] * inv;
                    v1.x = fs1 + cs0 - acc[im][in][2] * inv;
                    v1.y = fs1 + cs1 - acc[im][in][3] * inv;
                    *reinterpret_cast<float2*>(out + (size_t)gm * K_ROWS + gn)       = v0;
                    *reinterpret_cast<float2*>(out + (size_t)(gm + 8) * K_ROWS + gn) = v1;
                }
            }
#pragma unroll
            for (int im = 0; im < 4; im++)
#pragma unroll
                for (int in = 0; in < 4; in++)
#pragma unroll
                    for (int c = 0; c < 4; c++)
                        acc[im][in][c] = 0.f;
        }
    }
}

// ---------------------------------------------------------------------------
extern "C" void kernel_launch(void* const* d_in, const int* in_sizes, int n_in,
                              void* d_out, int out_size) {
    const float* feat = (const float*)d_in[0];
    const float* cent = (const float*)d_in[1];
    float* out = (float*)d_out;

    cudaFuncSetAttribute(fused_dist_kernel,
                         cudaFuncAttributeMaxDynamicSharedMemorySize, SM_ALLOC);

    fused_dist_kernel<<<GRID_P, 256, SM_ALLOC>>>(feat, cent, out);
}

// round 16
// speedup vs baseline: 1.0617x; 1.0617x over previous
#include <cuda_runtime.h>
#include <cuda_bf16.h>
#include <cuda_fp8.h>
#include <cstdint>

// ---------------------------------------------------------------------------
// Problem constants
// ---------------------------------------------------------------------------
#define N_ROWS 16384
#define K_ROWS 2048
#define D_DIM  1024

#define BM 128
#define BN 128
#define BK 128                  // fp8 -> 128 B per smem row (SW128 atom)
#define KT_PER_TILE 8           // D / BK
#define NTILES 2048             // (N/BM) * (K/BN)
#define TN 16                   // tiles along n
#define GRID_P 296              // persistent CTAs (2 per SM)
#define STAGES 3
#define A_STAGE_BYTES (BM * 128)                      // 16 KB
#define B_STAGE_BYTES (BN * 128)                      // 16 KB
#define STAGE_BYTES (A_STAGE_BYTES + B_STAGE_BYTES)   // 32 KB
#define SM_ALLOC (STAGES * STAGE_BYTES)               // 96 KB -> 2 CTAs/SM

// fp8 mirrors + squared norms (device globals: allocation-free scratch)
// feat scaled by 2 (exact), cent scaled by 256 (exact):
//   acc = 512*feat.cent -> out = fs + cs - acc/256
__device__ uint8_t g_feat_f8[(size_t)N_ROWS * D_DIM];   // 16 MB
__device__ uint8_t g_cent_f8[(size_t)K_ROWS * D_DIM];   //  2 MB
__device__ float g_feat_sq[N_ROWS];
__device__ float g_cent_sq[K_ROWS];

// ---------------------------------------------------------------------------
// helpers
// ---------------------------------------------------------------------------
__device__ __forceinline__ void cp_async16(uint32_t saddr, const void* gaddr) {
    asm volatile("cp.async.cg.shared.global [%0], [%1], 16;" :: "r"(saddr), "l"(gaddr));
}

__device__ __forceinline__ void ldsm_x4(uint32_t* r, uint32_t addr) {
    asm volatile("ldmatrix.sync.aligned.m8n8.x4.shared.b16 {%0,%1,%2,%3}, [%4];"
                 : "=r"(r[0]), "=r"(r[1]), "=r"(r[2]), "=r"(r[3]) : "r"(addr));
}

__device__ __forceinline__ void mma_fp8(float* c, const uint32_t* a,
                                        uint32_t b0, uint32_t b1) {
    asm volatile(
        "mma.sync.aligned.m16n8k32.row.col.f32.e4m3.e4m3.f32 "
        "{%0,%1,%2,%3}, {%4,%5,%6,%7}, {%8,%9}, {%0,%1,%2,%3};\n"
        : "+f"(c[0]), "+f"(c[1]), "+f"(c[2]), "+f"(c[3])
        : "r"(a[0]), "r"(a[1]), "r"(a[2]), "r"(a[3]), "r"(b0), "r"(b1));
}

// try_wait with nanosleep backoff: spinning warps previously accounted for
// ~97% of ALL issued instructions, flooding the MIO path with TRYWAIT ops
// that contend with LDSM / cp.async stores. Sleep between attempts.
__device__ __forceinline__ void mbar_wait(uint32_t mbar, uint32_t parity) {
    while (true) {
        uint32_t done;
        asm volatile(
            "{\n\t.reg .pred p;\n\t"
            "mbarrier.try_wait.parity.acquire.cta.shared::cta.b64 p, [%1], %2;\n\t"
            "selp.b32 %0, 1, 0, p;\n\t}"
            : "=r"(done) : "r"(mbar), "r"(parity) : "memory");
        if (done) return;
        __nanosleep(128);
    }
}

// ---------------------------------------------------------------------------
// fp32 -> fp8 conversion fused with row squared-norms. One warp per row.
// Each lane handles 2 adjacent 16B chunks per iter -> coalesced STG.64 out.
// ---------------------------------------------------------------------------
__global__ void __launch_bounds__(512, 2)
convert_norms_kernel(const float* __restrict__ feat,
                     const float* __restrict__ cent) {
    int grow = blockIdx.x * 16 + (threadIdx.x >> 5);
    int lane = threadIdx.x & 31;
    const float* src;
    uint8_t* dst;
    float* sq;
    int row;
    float scale;
    if (grow < N_ROWS) { src = feat; dst = g_feat_f8; sq = g_feat_sq; row = grow; scale = 2.f; }
    else               { src = cent; dst = g_cent_f8; sq = g_cent_sq; row = grow - N_ROWS; scale = 256.f; }

    const float4* p = reinterpret_cast<const float4*>(src) + (size_t)row * (D_DIM / 4);
    uint2* d = reinterpret_cast<uint2*>(dst + (size_t)row * D_DIM);
    float s = 0.f;
#pragma unroll
    for (int it = 0; it < 4; it++) {
        int c = it * 64 + lane * 2;
        float4 v0 = p[c];
        float4 v1 = p[c + 1];
        s += v0.x * v0.x + v0.y * v0.y + v0.z * v0.z + v0.w * v0.w;
        s += v1.x * v1.x + v1.y * v1.y + v1.z * v1.z + v1.w * v1.w;
        uint16_t a0 = __nv_cvt_float2_to_fp8x2(make_float2(v0.x * scale, v0.y * scale),
                                               __NV_SATFINITE, __NV_E4M3);
        uint16_t a1 = __nv_cvt_float2_to_fp8x2(make_float2(v0.z * scale, v0.w * scale),
                                               __NV_SATFINITE, __NV_E4M3);
        uint16_t a2 = __nv_cvt_float2_to_fp8x2(make_float2(v1.x * scale, v1.y * scale),
                                               __NV_SATFINITE, __NV_E4M3);
        uint16_t a3 = __nv_cvt_float2_to_fp8x2(make_float2(v1.z * scale, v1.w * scale),
                                               __NV_SATFINITE, __NV_E4M3);
        uint2 u;
        u.x = (uint32_t)a0 | ((uint32_t)a1 << 16);
        u.y = (uint32_t)a2 | ((uint32_t)a3 << 16);
        d[it * 32 + lane] = u;
    }
#pragma unroll
    for (int o = 16; o > 0; o >>= 1) s += __shfl_xor_sync(0xffffffffu, s, o);
    if (lane == 0) sq[row] = s;
}

// ---------------------------------------------------------------------------
// Persistent FP8 distance GEMM (R9/R13 proven-best mainloop, verbatim except
// the backoff in mbar_wait).
// ---------------------------------------------------------------------------
__global__ void __launch_bounds__(256, 2)
dist_gemm_kernel(float* __restrict__ out) {
    extern __shared__ __align__(1024) char smem[];
    __shared__ __align__(8) uint64_t mbars[2 * STAGES];   // [full0..2, empty0..2]
    const uint32_t smem_u = (uint32_t)__cvta_generic_to_shared(smem);
    const uint32_t mb_u   = (uint32_t)__cvta_generic_to_shared(mbars);

    const int tid  = threadIdx.x;
    const int warp = tid >> 5;
    const int lane = tid & 31;
    const int bid  = blockIdx.x;

    const int wm = (warp >> 2) * 64;
    const int wn = (warp & 3) * 32;

    if (tid == 0) {
#pragma unroll
        for (int s = 0; s < STAGES; s++) {
            asm volatile("mbarrier.init.shared.b64 [%0], 256;"
                         :: "r"(mb_u + s * 8) : "memory");                 // full
            asm volatile("mbarrier.init.shared.b64 [%0], 8;"
                         :: "r"(mb_u + (STAGES + s) * 8) : "memory");      // empty
        }
    }
    __syncthreads();

    // --- producer addressing ---
    const int ld_row = tid >> 1;
    const int ld_q0  = (tid & 1) * 4;
    const uint32_t ld_sw_row = ld_row * 128;
    const uint32_t ld_rx     = (ld_row & 7) << 4;

    auto produce = [&](int s, int st) {
        const int t  = bid + (st >> 3) * GRID_P;
        const int kt = st & 7;
        const int m0 = (t >> 4) << 7;
        const int n0 = (t & (TN - 1)) << 7;
        const uint32_t abase = smem_u + s * STAGE_BYTES;
        const uint32_t bbase = abase + A_STAGE_BYTES;
        const uint8_t* ag = g_feat_f8 + (size_t)(m0 + ld_row) * D_DIM + kt * BK + ld_q0 * 16;
        const uint8_t* bg = g_cent_f8 + (size_t)(n0 + ld_row) * D_DIM + kt * BK + ld_q0 * 16;
#pragma unroll
        for (int j = 0; j < 4; j++) {
            uint32_t so = ld_sw_row + ((((ld_q0 + j) * 16) ^ ld_rx));
            cp_async16(abase + so, ag + j * 16);
            cp_async16(bbase + so, bg + j * 16);
        }
        asm volatile("cp.async.mbarrier.arrive.noinc.shared::cta.b64 [%0];"
                     :: "r"(mb_u + s * 8) : "memory");
    };

    // --- consumer addressing (constant parts) ---
    const int fr_lo = lane & 15;
    const uint32_t fr_hi16 = (lane >> 4) * 16;

    uint32_t a_rowb[4], a_rx[4], b_rowb[2], b_rx[2];
#pragma unroll
    for (int im = 0; im < 4; im++) {
        int r = wm + im * 16 + fr_lo;
        a_rowb[im] = r * 128;
        a_rx[im]   = (r & 7) << 4;
    }
#pragma unroll
    for (int ib = 0; ib < 2; ib++) {
        int r = wn + ib * 16 + fr_lo;
        b_rowb[ib] = r * 128;
        b_rx[ib]   = (r & 7) << 4;
    }

    float acc[4][4][4] = {};

    const int ntiles = (NTILES - bid + GRID_P - 1) / GRID_P;
    const int nsteps = ntiles * KT_PER_TILE;

    int ps = 0, pph = 1;
    int cs = 0, cph = 0;

#pragma unroll
    for (int k = 0; k < STAGES - 1; k++) {
        mbar_wait(mb_u + (STAGES + ps) * 8, (uint32_t)pph);
        produce(ps, k);
        if (++ps == STAGES) { ps = 0; pph ^= 1; }
    }

    for (int st = 0; st < nsteps; st++) {
        mbar_wait(mb_u + cs * 8, (uint32_t)cph);
        const uint32_t abase = smem_u + cs * STAGE_BYTES;
        const uint32_t bbase = abase + A_STAGE_BYTES;

#pragma unroll
        for (int ks = 0; ks < 4; ks++) {
            const int kse = (ks + warp) & 3;
            const uint32_t kb = kse * 32 + fr_hi16;
            uint32_t a[4][4], bq[2][4];
#pragma unroll
            for (int im = 0; im < 4; im++)
                ldsm_x4(a[im], abase + a_rowb[im] + (kb ^ a_rx[im]));
#pragma unroll
            for (int ib = 0; ib < 2; ib++)
                ldsm_x4(bq[ib], bbase + b_rowb[ib] + (kb ^ b_rx[ib]));
#pragma unroll
            for (int im = 0; im < 4; im++) {
#pragma unroll
                for (int ib = 0; ib < 2; ib++) {
                    mma_fp8(acc[im][2 * ib],     a[im], bq[ib][0], bq[ib][2]);
                    mma_fp8(acc[im][2 * ib + 1], a[im], bq[ib][1], bq[ib][3]);
                }
            }
        }

        if (lane == 0) {
            asm volatile("mbarrier.arrive.shared.b64 _, [%0];"
                         :: "r"(mb_u + (STAGES + cs) * 8) : "memory");
        }
        if (++cs == STAGES) { cs = 0; cph ^= 1; }

        if (st + STAGES - 1 < nsteps) {
            mbar_wait(mb_u + (STAGES + ps) * 8, (uint32_t)pph);
            produce(ps, st + STAGES - 1);
            if (++ps == STAGES) { ps = 0; pph ^= 1; }
        }

        if ((st & 7) == 7) {
            // ---- epilogue for finished tile; ring stays warm ----
            const int t  = bid + (st >> 3) * GRID_P;
            const int m0 = (t >> 4) << 7;
            const int n0 = (t & (TN - 1)) << 7;
            const float inv = 1.0f / 256.0f;
            const int g = lane >> 2;
            const int tt = lane & 3;
#pragma unroll
            for (int im = 0; im < 4; im++) {
                int gm = m0 + wm + im * 16 + g;
                float fs0 = g_feat_sq[gm];
                float fs1 = g_feat_sq[gm + 8];
#pragma unroll
                for (int in = 0; in < 4; in++) {
                    int gn = n0 + wn + in * 8 + 2 * tt;
                    float cs0 = g_cent_sq[gn];
                    float cs1 = g_cent_sq[gn + 1];
                    float2 v0, v1;
                    v0.x = fs0 + cs0 - acc[im][in][0] * inv;
                    v0.y = fs0 + cs1 - acc[im][in][1] * inv;
                    v1.x = fs1 + cs0 - acc[im][in][2] * inv;
                    v1.y = fs1 + cs1 - acc[im][in][3] * inv;
                    *reinterpret_cast<float2*>(out + (size_t)gm * K_ROWS + gn)       = v0;
                    *reinterpret_cast<float2*>(out + (size_t)(gm + 8) * K_ROWS + gn) = v1;
                }
            }
#pragma unroll
            for (int im = 0; im < 4; im++)
#pragma unroll
                for (int in = 0; in < 4; in++)
#pragma unroll
                    for (int c = 0; c < 4; c++)
                        acc[im][in][c] = 0.f;
        }
    }
}

// ---------------------------------------------------------------------------
extern "C" void kernel_launch(void* const* d_in, const int* in_sizes, int n_in,
                              void* d_out, int out_size) {
    const float* feat = (const float*)d_in[0];
    const float* cent = (const float*)d_in[1];
    float* out = (float*)d_out;

    cudaFuncSetAttribute(dist_gemm_kernel,
                         cudaFuncAttributeMaxDynamicSharedMemorySize, SM_ALLOC);

    convert_norms_kernel<<<(N_ROWS + K_ROWS) / 16, 512>>>(feat, cent);

    dist_gemm_kernel<<<GRID_P, 256, SM_ALLOC>>>(out);
}